// round 4
// baseline (speedup 1.0000x reference)
#include <cuda_runtime.h>

#define N_NODES  250000
#define N_EDGES  4000000
#define N_GRAPHS 512

// ---------------- scratch (device globals; no allocation allowed) ----------------
__device__ __align__(16) float4 g_p  [N_NODES * 4];  // projected features (max 16 f/node)
__device__ __align__(16) float4 g_tmp[N_NODES * 4];  // aggregation accumulator
__device__ __align__(16) float4 g_h1 [N_NODES * 4];  // h1 [N,16]
__device__ __align__(16) float4 g_h2 [N_NODES * 2];  // h2 [N,8]
__device__ __align__(16) float  g_cnt[N_NODES];      // in-degree
__device__ __align__(16) int2   g_edge[N_EDGES];     // (src,dst) as int32
__device__ __align__(16) float  g_pool[N_GRAPHS * 4];
__device__ __align__(16) float  g_gcnt[N_GRAPHS];

__device__ __forceinline__ float lrelu(float v) { return v > 0.f ? v : 0.01f * v; }

// ---------------- init: zero accumulators ----------------
__global__ void k_init() {
    int i = blockIdx.x * blockDim.x + threadIdx.x;
    int stride = gridDim.x * blockDim.x;
    float4 z = make_float4(0.f, 0.f, 0.f, 0.f);
    for (int j = i; j < N_NODES * 4; j += stride) g_tmp[j] = z;
    for (int j = i; j < N_NODES / 4; j += stride) ((float4*)g_cnt)[j] = z;
    for (int j = i; j < N_GRAPHS;    j += stride) ((float4*)g_pool)[j] = z;
    for (int j = i; j < N_GRAPHS/4;  j += stride) ((float4*)g_gcnt)[j] = z;
}

// ---------------- edge prep: int32 pack + degree count ----------------
__global__ void k_prep(const int* __restrict__ ei) {
    int e = blockIdx.x * blockDim.x + threadIdx.x;
    if (e >= N_EDGES) return;
    int s = ei[e];
    int d = ei[N_EDGES + e];
    g_edge[e] = make_int2(s, d);
    atomicAdd(&g_cnt[d], 1.0f);
}

// ---------------- projection: p1 = x @ W1l (13x16) ----------------
__global__ void k_proj1(const float* __restrict__ x, const float* __restrict__ W1l) {
    __shared__ float sW[13 * 16];
    if (threadIdx.x < 13 * 16) sW[threadIdx.x] = W1l[threadIdx.x];
    __syncthreads();
    int i = blockIdx.x * blockDim.x + threadIdx.x;
    if (i >= N_NODES) return;
    float xv[13];
    const float* xr = x + (long long)i * 13;
    #pragma unroll
    for (int k = 0; k < 13; k++) xv[k] = xr[k];
    float o[16];
    #pragma unroll
    for (int j = 0; j < 16; j++) {
        float a = 0.f;
        #pragma unroll
        for (int k = 0; k < 13; k++) a += xv[k] * sW[k * 16 + j];
        o[j] = a;
    }
    float4* op = g_p + i * 4;
    #pragma unroll
    for (int c = 0; c < 4; c++)
        op[c] = make_float4(o[c*4+0], o[c*4+1], o[c*4+2], o[c*4+3]);
}

// ---------------- edge scatter (D4 = float4 chunks per node) ----------------
template <int D4>
__global__ void k_scatter() {
    int e = blockIdx.x * blockDim.x + threadIdx.x;
    if (e >= N_EDGES) return;
    int2 sd = g_edge[e];
    const float4* sp = g_p + (long long)sd.x * D4;
    float*        dp = (float*)(g_tmp + (long long)sd.y * D4);
    #pragma unroll
    for (int c = 0; c < D4; c++) {
        float4 v = sp[c];
        atomicAdd(dp + c * 4 + 0, v.x);
        atomicAdd(dp + c * 4 + 1, v.y);
        atomicAdd(dp + c * 4 + 2, v.z);
        atomicAdd(dp + c * 4 + 3, v.w);
    }
}

// ---------------- node update 1: h1 = lrelu(agg + b1 + x@W1r); p2 = h1@W2l ----------------
__global__ void k_node1(const float* __restrict__ x, const float* __restrict__ W1r,
                        const float* __restrict__ b1, const float* __restrict__ W2l) {
    __shared__ float sW1r[13 * 16], sb1[16], sW2l[16 * 8];
    if (threadIdx.x < 13 * 16) sW1r[threadIdx.x] = W1r[threadIdx.x];
    if (threadIdx.x < 16) sb1[threadIdx.x] = b1[threadIdx.x];
    if (threadIdx.x < 16 * 8) sW2l[threadIdx.x] = W2l[threadIdx.x];
    __syncthreads();
    int i = blockIdx.x * blockDim.x + threadIdx.x;
    if (i >= N_NODES) return;
    float4 z = make_float4(0.f, 0.f, 0.f, 0.f);
    float t[16];
    float4* tp = g_tmp + i * 4;
    #pragma unroll
    for (int c = 0; c < 4; c++) {
        float4 v = tp[c];
        t[c*4+0] = v.x; t[c*4+1] = v.y; t[c*4+2] = v.z; t[c*4+3] = v.w;
        tp[c] = z;  // reset accumulator for next layer
    }
    float inv = 1.0f / fmaxf(g_cnt[i], 1.0f);
    float xv[13];
    const float* xr = x + (long long)i * 13;
    #pragma unroll
    for (int k = 0; k < 13; k++) xv[k] = xr[k];
    float h[16];
    #pragma unroll
    for (int j = 0; j < 16; j++) {
        float a = t[j] * inv + sb1[j];
        #pragma unroll
        for (int k = 0; k < 13; k++) a += xv[k] * sW1r[k * 16 + j];
        h[j] = lrelu(a);
    }
    float4* hp = g_h1 + i * 4;
    #pragma unroll
    for (int c = 0; c < 4; c++)
        hp[c] = make_float4(h[c*4+0], h[c*4+1], h[c*4+2], h[c*4+3]);
    // p2 = h1 @ W2l  (16x8)
    float p2[8];
    #pragma unroll
    for (int j = 0; j < 8; j++) {
        float a = 0.f;
        #pragma unroll
        for (int k = 0; k < 16; k++) a += h[k] * sW2l[k * 8 + j];
        p2[j] = a;
    }
    float4* pp = g_p + i * 2;
    pp[0] = make_float4(p2[0], p2[1], p2[2], p2[3]);
    pp[1] = make_float4(p2[4], p2[5], p2[6], p2[7]);
}

// ---------------- node update 2: h2 = lrelu(agg + b2 + h1@W2r); p3 = h2@W3l ----------------
__global__ void k_node2(const float* __restrict__ W2r, const float* __restrict__ b2,
                        const float* __restrict__ W3l) {
    __shared__ float sW2r[16 * 8], sb2[8], sW3l[8 * 4];
    if (threadIdx.x < 16 * 8) sW2r[threadIdx.x] = W2r[threadIdx.x];
    if (threadIdx.x < 8) sb2[threadIdx.x] = b2[threadIdx.x];
    if (threadIdx.x < 8 * 4) sW3l[threadIdx.x] = W3l[threadIdx.x];
    __syncthreads();
    int i = blockIdx.x * blockDim.x + threadIdx.x;
    if (i >= N_NODES) return;
    float4 z = make_float4(0.f, 0.f, 0.f, 0.f);
    float t[8];
    float4* tp = g_tmp + i * 2;
    #pragma unroll
    for (int c = 0; c < 2; c++) {
        float4 v = tp[c];
        t[c*4+0] = v.x; t[c*4+1] = v.y; t[c*4+2] = v.z; t[c*4+3] = v.w;
        tp[c] = z;
    }
    float inv = 1.0f / fmaxf(g_cnt[i], 1.0f);
    float h1v[16];
    const float4* hp = g_h1 + i * 4;
    #pragma unroll
    for (int c = 0; c < 4; c++) {
        float4 v = hp[c];
        h1v[c*4+0] = v.x; h1v[c*4+1] = v.y; h1v[c*4+2] = v.z; h1v[c*4+3] = v.w;
    }
    float h[8];
    #pragma unroll
    for (int j = 0; j < 8; j++) {
        float a = t[j] * inv + sb2[j];
        #pragma unroll
        for (int k = 0; k < 16; k++) a += h1v[k] * sW2r[k * 8 + j];
        h[j] = lrelu(a);
    }
    float4* h2p = g_h2 + i * 2;
    h2p[0] = make_float4(h[0], h[1], h[2], h[3]);
    h2p[1] = make_float4(h[4], h[5], h[6], h[7]);
    float p3[4];
    #pragma unroll
    for (int j = 0; j < 4; j++) {
        float a = 0.f;
        #pragma unroll
        for (int k = 0; k < 8; k++) a += h[k] * sW3l[k * 4 + j];
        p3[j] = a;
    }
    g_p[i] = make_float4(p3[0], p3[1], p3[2], p3[3]);
}

// ---------------- node update 3 + pooling ----------------
__global__ void k_node3_pool(const int* __restrict__ batch,
                             const float* __restrict__ W3r, const float* __restrict__ b3) {
    __shared__ float sW[8 * 4], sb[4];
    if (threadIdx.x < 32) sW[threadIdx.x] = W3r[threadIdx.x];
    if (threadIdx.x < 4) sb[threadIdx.x] = b3[threadIdx.x];
    __syncthreads();
    int i = blockIdx.x * blockDim.x + threadIdx.x;
    unsigned mask = __ballot_sync(0xffffffffu, i < N_NODES);
    if (i >= N_NODES) return;
    float4 t = g_tmp[i];
    float tv[4] = {t.x, t.y, t.z, t.w};
    float inv = 1.0f / fmaxf(g_cnt[i], 1.0f);
    float h2v[8];
    const float4* hp = g_h2 + i * 2;
    float4 a0 = hp[0], a1 = hp[1];
    h2v[0]=a0.x; h2v[1]=a0.y; h2v[2]=a0.z; h2v[3]=a0.w;
    h2v[4]=a1.x; h2v[5]=a1.y; h2v[6]=a1.z; h2v[7]=a1.w;
    float o[4];
    #pragma unroll
    for (int j = 0; j < 4; j++) {
        float a = tv[j] * inv + sb[j];
        #pragma unroll
        for (int k = 0; k < 8; k++) a += h2v[k] * sW[k * 4 + j];
        o[j] = a;
    }
    int g = batch[i];
    bool full = (mask == 0xffffffffu);
    int g0 = __shfl_sync(mask, g, 0);
    bool uni = full && __all_sync(0xffffffffu, g == g0);
    if (uni) {
        float c = 1.0f;
        #pragma unroll
        for (int off = 16; off; off >>= 1) {
            #pragma unroll
            for (int j = 0; j < 4; j++) o[j] += __shfl_xor_sync(0xffffffffu, o[j], off);
            c += __shfl_xor_sync(0xffffffffu, c, off);
        }
        if ((threadIdx.x & 31) == 0) {
            #pragma unroll
            for (int j = 0; j < 4; j++) atomicAdd(&g_pool[g * 4 + j], o[j]);
            atomicAdd(&g_gcnt[g], c);
        }
    } else {
        #pragma unroll
        for (int j = 0; j < 4; j++) atomicAdd(&g_pool[g * 4 + j], o[j]);
        atomicAdd(&g_gcnt[g], 1.0f);
    }
}

// ---------------- final: out = [mean_pool, add_pool] @ Wc + bc ----------------
__global__ void k_final(const float* __restrict__ Wc, const float* __restrict__ bc,
                        float* __restrict__ out) {
    int g = blockIdx.x * blockDim.x + threadIdx.x;
    if (g >= N_GRAPHS) return;
    float gc = fmaxf(g_gcnt[g], 1.0f);
    float acc = bc[0];
    #pragma unroll
    for (int j = 0; j < 4; j++) {
        float ap = g_pool[g * 4 + j];
        acc += (ap / gc) * Wc[j] + ap * Wc[4 + j];
    }
    out[g] = acc;
}

extern "C" void kernel_launch(void* const* d_in, const int* in_sizes, int n_in,
                              void* d_out, int out_size) {
    const float* x     = (const float*)d_in[0];
    const int*   eidx  = (const int*)d_in[1];   // int64 in reference, int32 on device (JAX x64 off)
    const int*   batch = (const int*)d_in[2];
    const float* W1l = (const float*)d_in[3];
    const float* b1  = (const float*)d_in[4];
    const float* W1r = (const float*)d_in[5];
    const float* W2l = (const float*)d_in[6];
    const float* b2  = (const float*)d_in[7];
    const float* W2r = (const float*)d_in[8];
    const float* W3l = (const float*)d_in[9];
    const float* b3  = (const float*)d_in[10];
    const float* W3r = (const float*)d_in[11];
    const float* Wc  = (const float*)d_in[12];
    const float* bc  = (const float*)d_in[13];
    float* out = (float*)d_out;

    const int TB = 256;
    const int nblk = (N_NODES + TB - 1) / TB;
    const int eblk = (N_EDGES + TB - 1) / TB;

    k_init<<<1024, TB>>>();
    k_prep<<<eblk, TB>>>(eidx);
    k_proj1<<<nblk, TB>>>(x, W1l);
    k_scatter<4><<<eblk, TB>>>();
    k_node1<<<nblk, TB>>>(x, W1r, b1, W2l);
    k_scatter<2><<<eblk, TB>>>();
    k_node2<<<nblk, TB>>>(W2r, b2, W3l);
    k_scatter<1><<<eblk, TB>>>();
    k_node3_pool<<<nblk, TB>>>(batch, W3r, b3);
    k_final<<<2, TB>>>(Wc, bc, out);
}

// round 6
// speedup vs baseline: 2.7110x; 2.7110x over previous
#include <cuda_runtime.h>

#define N_NODES  250000
#define N_EDGES  4000000
#define N_GRAPHS 512

#define SCAN_CHUNK 1024
#define SCAN_NBLK  ((N_NODES + SCAN_CHUNK - 1) / SCAN_CHUNK)   // 245

// ---------------- scratch (device globals; no allocation allowed) ----------------
__device__ __align__(16) float4 g_p  [N_NODES * 4];  // layer messages (dense)
__device__ __align__(16) float4 g_tmp[N_NODES * 4];  // p2 [0,2N) + r2 [2N,4N)
__device__ __align__(16) float4 g_r1 [N_NODES * 4];  // r1 = x@W1r + b1
__device__ __align__(16) int    g_deg[N_NODES];
__device__ __align__(16) int    g_off[N_NODES];
__device__ __align__(16) int    g_cur[N_NODES];
__device__ __align__(16) int    g_csr[N_EDGES];
__device__ __align__(16) int    g_bsum[SCAN_NBLK + 16];
__device__ __align__(16) float  g_pool[N_GRAPHS * 4];
__device__ __align__(16) float  g_gcnt[N_GRAPHS];

__device__ __forceinline__ float lrelu(float v) { return v > 0.f ? v : 0.01f * v; }
__device__ __forceinline__ void f4acc(float4& a, float4 b) {
    a.x += b.x; a.y += b.y; a.z += b.z; a.w += b.w;
}

// ---------------- zero ----------------
__global__ void k_zero() {
    int i = blockIdx.x * blockDim.x + threadIdx.x;
    int stride = gridDim.x * blockDim.x;
    for (int j = i; j < N_NODES / 4; j += stride) ((int4*)g_deg)[j] = make_int4(0,0,0,0);
    for (int j = i; j < N_GRAPHS;    j += stride) ((float4*)g_pool)[j] = make_float4(0,0,0,0);
    for (int j = i; j < N_GRAPHS/4;  j += stride) ((float4*)g_gcnt)[j] = make_float4(0,0,0,0);
}

// ---------------- degree count ----------------
__global__ void k_count(const int* __restrict__ ei) {
    int e = blockIdx.x * blockDim.x + threadIdx.x;
    if (e >= N_EDGES) return;
    atomicAdd(&g_deg[ei[N_EDGES + e]], 1);
}

// ---------------- scan 1: per-block local exclusive scan + block sums ----------------
__global__ void k_scan1() {
    __shared__ int s[256];
    int t = threadIdx.x;
    int base = blockIdx.x * SCAN_CHUNK + t * 4;
    int d0 = (base + 0 < N_NODES) ? g_deg[base + 0] : 0;
    int d1 = (base + 1 < N_NODES) ? g_deg[base + 1] : 0;
    int d2 = (base + 2 < N_NODES) ? g_deg[base + 2] : 0;
    int d3 = (base + 3 < N_NODES) ? g_deg[base + 3] : 0;
    int tot = d0 + d1 + d2 + d3;
    s[t] = tot;
    __syncthreads();
    int v = tot;
    #pragma unroll
    for (int off = 1; off < 256; off <<= 1) {
        int u = (t >= off) ? s[t - off] : 0;
        __syncthreads();
        v += u; s[t] = v;
        __syncthreads();
    }
    int ex = v - tot;  // exclusive prefix of this thread within block
    if (base + 0 < N_NODES) g_off[base + 0] = ex;
    if (base + 1 < N_NODES) g_off[base + 1] = ex + d0;
    if (base + 2 < N_NODES) g_off[base + 2] = ex + d0 + d1;
    if (base + 3 < N_NODES) g_off[base + 3] = ex + d0 + d1 + d2;
    if (t == 255) g_bsum[blockIdx.x] = v;  // block total
}

// ---------------- scan 2: exclusive scan of block sums (single block) ----------------
__global__ void k_scan2() {
    __shared__ int s[256];
    int t = threadIdx.x;
    int val = (t < SCAN_NBLK) ? g_bsum[t] : 0;
    s[t] = val;
    __syncthreads();
    int v = val;
    #pragma unroll
    for (int off = 1; off < 256; off <<= 1) {
        int u = (t >= off) ? s[t - off] : 0;
        __syncthreads();
        v += u; s[t] = v;
        __syncthreads();
    }
    if (t < SCAN_NBLK) g_bsum[t] = v - val;  // exclusive
}

// ---------------- scan 3: add block base; init cursors ----------------
__global__ void k_scan3() {
    int i = blockIdx.x * blockDim.x + threadIdx.x;
    if (i >= N_NODES) return;
    int off = g_off[i] + g_bsum[i / SCAN_CHUNK];
    g_off[i] = off;
    g_cur[i] = off;
}

// ---------------- CSR fill ----------------
__global__ void k_fill(const int* __restrict__ ei) {
    int e = blockIdx.x * blockDim.x + threadIdx.x;
    if (e >= N_EDGES) return;
    int s = ei[e];
    int d = ei[N_EDGES + e];
    int slot = atomicAdd(&g_cur[d], 1);
    g_csr[slot] = s;
}

// ---------------- proj1: p1 = x@W1l -> g_p ; r1 = x@W1r + b1 -> g_r1 ----------------
__global__ void k_proj1(const float* __restrict__ x, const float* __restrict__ W1l,
                        const float* __restrict__ W1r, const float* __restrict__ b1) {
    __shared__ float sWl[13 * 16], sWr[13 * 16], sb[16];
    if (threadIdx.x < 13 * 16) { sWl[threadIdx.x] = W1l[threadIdx.x]; sWr[threadIdx.x] = W1r[threadIdx.x]; }
    if (threadIdx.x < 16) sb[threadIdx.x] = b1[threadIdx.x];
    __syncthreads();
    int i = blockIdx.x * blockDim.x + threadIdx.x;
    if (i >= N_NODES) return;
    float xv[13];
    const float* xr = x + (size_t)i * 13;
    #pragma unroll
    for (int k = 0; k < 13; k++) xv[k] = xr[k];
    float p[16], r[16];
    #pragma unroll
    for (int j = 0; j < 16; j++) {
        float a = 0.f, c = sb[j];
        #pragma unroll
        for (int k = 0; k < 13; k++) { a += xv[k] * sWl[k * 16 + j]; c += xv[k] * sWr[k * 16 + j]; }
        p[j] = a; r[j] = c;
    }
    float4* pp = g_p  + (size_t)i * 4;
    float4* rp = g_r1 + (size_t)i * 4;
    #pragma unroll
    for (int c = 0; c < 4; c++) {
        pp[c] = make_float4(p[c*4+0], p[c*4+1], p[c*4+2], p[c*4+3]);
        rp[c] = make_float4(r[c*4+0], r[c*4+1], r[c*4+2], r[c*4+3]);
    }
}

// ---------------- pull1: agg(p1) -> h1 -> p2 (g_tmp[0,2N)), r2 (g_tmp[2N,4N)) ----------------
__global__ void k_pull1(const float* __restrict__ W2l, const float* __restrict__ W2r,
                        const float* __restrict__ b2) {
    __shared__ float sWl[16 * 8], sWr[16 * 8], sb[8];
    if (threadIdx.x < 128) { sWl[threadIdx.x] = W2l[threadIdx.x]; sWr[threadIdx.x] = W2r[threadIdx.x]; }
    if (threadIdx.x < 8) sb[threadIdx.x] = b2[threadIdx.x];
    __syncthreads();
    int i = blockIdx.x * blockDim.x + threadIdx.x;
    if (i >= N_NODES) return;
    int deg = g_deg[i];
    int e = g_off[i], end = e + deg;
    float4 a0 = make_float4(0,0,0,0), a1 = a0, a2 = a0, a3 = a0;
    if ((e & 1) && e < end) {
        const float4* r = g_p + (size_t)g_csr[e] * 4;
        f4acc(a0, r[0]); f4acc(a1, r[1]); f4acc(a2, r[2]); f4acc(a3, r[3]);
        e++;
    }
    for (; e + 2 <= end; e += 2) {
        int2 s2 = *(const int2*)(g_csr + e);
        const float4* ra = g_p + (size_t)s2.x * 4;
        const float4* rb = g_p + (size_t)s2.y * 4;
        float4 u0 = ra[0], u1 = ra[1], u2 = ra[2], u3 = ra[3];
        float4 v0 = rb[0], v1 = rb[1], v2 = rb[2], v3 = rb[3];
        f4acc(a0, u0); f4acc(a1, u1); f4acc(a2, u2); f4acc(a3, u3);
        f4acc(a0, v0); f4acc(a1, v1); f4acc(a2, v2); f4acc(a3, v3);
    }
    if (e < end) {
        const float4* r = g_p + (size_t)g_csr[e] * 4;
        f4acc(a0, r[0]); f4acc(a1, r[1]); f4acc(a2, r[2]); f4acc(a3, r[3]);
    }
    float inv = 1.0f / fmaxf((float)deg, 1.0f);
    float agg[16] = {a0.x,a0.y,a0.z,a0.w, a1.x,a1.y,a1.z,a1.w,
                     a2.x,a2.y,a2.z,a2.w, a3.x,a3.y,a3.z,a3.w};
    const float4* r1p = g_r1 + (size_t)i * 4;
    float h[16];
    #pragma unroll
    for (int c = 0; c < 4; c++) {
        float4 rv = r1p[c];
        h[c*4+0] = lrelu(agg[c*4+0] * inv + rv.x);
        h[c*4+1] = lrelu(agg[c*4+1] * inv + rv.y);
        h[c*4+2] = lrelu(agg[c*4+2] * inv + rv.z);
        h[c*4+3] = lrelu(agg[c*4+3] * inv + rv.w);
    }
    float p[8], r[8];
    #pragma unroll
    for (int j = 0; j < 8; j++) {
        float a = 0.f, c = sb[j];
        #pragma unroll
        for (int k = 0; k < 16; k++) { a += h[k] * sWl[k * 8 + j]; c += h[k] * sWr[k * 8 + j]; }
        p[j] = a; r[j] = c;
    }
    float4* pp = g_tmp + (size_t)i * 2;
    float4* rp = g_tmp + (size_t)(N_NODES * 2) + (size_t)i * 2;
    pp[0] = make_float4(p[0],p[1],p[2],p[3]);
    pp[1] = make_float4(p[4],p[5],p[6],p[7]);
    rp[0] = make_float4(r[0],r[1],r[2],r[3]);
    rp[1] = make_float4(r[4],r[5],r[6],r[7]);
}

// ---------------- pull2: agg(p2) -> h2 -> p3 (g_p[0,N)), r3 (g_p[N,2N)) ----------------
__global__ void k_pull2(const float* __restrict__ W3l, const float* __restrict__ W3r,
                        const float* __restrict__ b3) {
    __shared__ float sWl[8 * 4], sWr[8 * 4], sb[4];
    if (threadIdx.x < 32) { sWl[threadIdx.x] = W3l[threadIdx.x]; sWr[threadIdx.x] = W3r[threadIdx.x]; }
    if (threadIdx.x < 4) sb[threadIdx.x] = b3[threadIdx.x];
    __syncthreads();
    int i = blockIdx.x * blockDim.x + threadIdx.x;
    if (i >= N_NODES) return;
    int deg = g_deg[i];
    int e = g_off[i], end = e + deg;
    float4 a0 = make_float4(0,0,0,0), a1 = a0;
    while ((e & 3) && e < end) {
        const float4* r = g_tmp + (size_t)g_csr[e] * 2;
        f4acc(a0, r[0]); f4acc(a1, r[1]);
        e++;
    }
    for (; e + 4 <= end; e += 4) {
        int4 s4 = *(const int4*)(g_csr + e);
        const float4* ra = g_tmp + (size_t)s4.x * 2;
        const float4* rb = g_tmp + (size_t)s4.y * 2;
        const float4* rc = g_tmp + (size_t)s4.z * 2;
        const float4* rd = g_tmp + (size_t)s4.w * 2;
        float4 u0 = ra[0], u1 = ra[1], v0 = rb[0], v1 = rb[1];
        float4 w0 = rc[0], w1 = rc[1], y0 = rd[0], y1 = rd[1];
        f4acc(a0, u0); f4acc(a1, u1); f4acc(a0, v0); f4acc(a1, v1);
        f4acc(a0, w0); f4acc(a1, w1); f4acc(a0, y0); f4acc(a1, y1);
    }
    for (; e < end; e++) {
        const float4* r = g_tmp + (size_t)g_csr[e] * 2;
        f4acc(a0, r[0]); f4acc(a1, r[1]);
    }
    float inv = 1.0f / fmaxf((float)deg, 1.0f);
    const float4* r2p = g_tmp + (size_t)(N_NODES * 2) + (size_t)i * 2;
    float4 rA = r2p[0], rB = r2p[1];
    float h[8];
    h[0] = lrelu(a0.x*inv + rA.x); h[1] = lrelu(a0.y*inv + rA.y);
    h[2] = lrelu(a0.z*inv + rA.z); h[3] = lrelu(a0.w*inv + rA.w);
    h[4] = lrelu(a1.x*inv + rB.x); h[5] = lrelu(a1.y*inv + rB.y);
    h[6] = lrelu(a1.z*inv + rB.z); h[7] = lrelu(a1.w*inv + rB.w);
    float p[4], r[4];
    #pragma unroll
    for (int j = 0; j < 4; j++) {
        float a = 0.f, c = sb[j];
        #pragma unroll
        for (int k = 0; k < 8; k++) { a += h[k] * sWl[k * 4 + j]; c += h[k] * sWr[k * 4 + j]; }
        p[j] = a; r[j] = c;
    }
    g_p[i] = make_float4(p[0], p[1], p[2], p[3]);
    g_p[N_NODES + i] = make_float4(r[0], r[1], r[2], r[3]);
}

// ---------------- pull3: agg(p3) + r3 -> o ; pooled ----------------
__global__ void k_pull3(const int* __restrict__ batch) {
    int i = blockIdx.x * blockDim.x + threadIdx.x;
    unsigned mask = __ballot_sync(0xffffffffu, i < N_NODES);
    if (i >= N_NODES) return;
    int deg = g_deg[i];
    int e = g_off[i], end = e + deg;
    float4 a0 = make_float4(0,0,0,0);
    while ((e & 3) && e < end) { f4acc(a0, g_p[g_csr[e]]); e++; }
    for (; e + 4 <= end; e += 4) {
        int4 s4 = *(const int4*)(g_csr + e);
        float4 u = g_p[s4.x], v = g_p[s4.y], w = g_p[s4.z], y = g_p[s4.w];
        f4acc(a0, u); f4acc(a0, v); f4acc(a0, w); f4acc(a0, y);
    }
    for (; e < end; e++) f4acc(a0, g_p[g_csr[e]]);
    float inv = 1.0f / fmaxf((float)deg, 1.0f);
    float4 rv = g_p[N_NODES + i];
    float o[4] = { a0.x*inv + rv.x, a0.y*inv + rv.y, a0.z*inv + rv.z, a0.w*inv + rv.w };
    int g = batch[i];
    bool full = (mask == 0xffffffffu);
    int g0 = __shfl_sync(mask, g, 0);
    bool uni = full && __all_sync(0xffffffffu, g == g0);
    if (uni) {
        float c = 1.0f;
        #pragma unroll
        for (int off = 16; off; off >>= 1) {
            #pragma unroll
            for (int j = 0; j < 4; j++) o[j] += __shfl_xor_sync(0xffffffffu, o[j], off);
            c += __shfl_xor_sync(0xffffffffu, c, off);
        }
        if ((threadIdx.x & 31) == 0) {
            #pragma unroll
            for (int j = 0; j < 4; j++) atomicAdd(&g_pool[g * 4 + j], o[j]);
            atomicAdd(&g_gcnt[g], c);
        }
    } else {
        #pragma unroll
        for (int j = 0; j < 4; j++) atomicAdd(&g_pool[g * 4 + j], o[j]);
        atomicAdd(&g_gcnt[g], 1.0f);
    }
}

// ---------------- final ----------------
__global__ void k_final(const float* __restrict__ Wc, const float* __restrict__ bc,
                        float* __restrict__ out) {
    int g = blockIdx.x * blockDim.x + threadIdx.x;
    if (g >= N_GRAPHS) return;
    float gc = fmaxf(g_gcnt[g], 1.0f);
    float acc = bc[0];
    #pragma unroll
    for (int j = 0; j < 4; j++) {
        float ap = g_pool[g * 4 + j];
        acc += (ap / gc) * Wc[j] + ap * Wc[4 + j];
    }
    out[g] = acc;
}

extern "C" void kernel_launch(void* const* d_in, const int* in_sizes, int n_in,
                              void* d_out, int out_size) {
    const float* x     = (const float*)d_in[0];
    const int*   eidx  = (const int*)d_in[1];   // int32 on device (JAX x64 off)
    const int*   batch = (const int*)d_in[2];
    const float* W1l = (const float*)d_in[3];
    const float* b1  = (const float*)d_in[4];
    const float* W1r = (const float*)d_in[5];
    const float* W2l = (const float*)d_in[6];
    const float* b2  = (const float*)d_in[7];
    const float* W2r = (const float*)d_in[8];
    const float* W3l = (const float*)d_in[9];
    const float* b3  = (const float*)d_in[10];
    const float* W3r = (const float*)d_in[11];
    const float* Wc  = (const float*)d_in[12];
    const float* bc  = (const float*)d_in[13];
    float* out = (float*)d_out;

    const int TB = 256;
    const int nblk = (N_NODES + TB - 1) / TB;
    const int eblk = (N_EDGES + TB - 1) / TB;

    k_zero <<<256, TB>>>();
    k_count<<<eblk, TB>>>(eidx);
    k_scan1<<<SCAN_NBLK, 256>>>();
    k_scan2<<<1, 256>>>();
    k_scan3<<<nblk, TB>>>();
    k_fill <<<eblk, TB>>>(eidx);
    k_proj1<<<nblk, TB>>>(x, W1l, W1r, b1);
    k_pull1<<<nblk, TB>>>(W2l, W2r, b2);
    k_pull2<<<nblk, TB>>>(W3l, W3r, b3);
    k_pull3<<<nblk, TB>>>(batch);
    k_final<<<2, TB>>>(Wc, bc, out);
}

// round 7
// speedup vs baseline: 3.3076x; 1.2201x over previous
#include <cuda_runtime.h>
#include <cuda_fp16.h>

#define N_NODES  250000
#define N_EDGES  4000000
#define N_GRAPHS 512

#define SCAN_CHUNK 1024
#define SCAN_NBLK  ((N_NODES + SCAN_CHUNK - 1) / SCAN_CHUNK)   // 245

// ---------------- scratch (device globals; no allocation allowed) ----------------
__device__ __align__(16) uint4  g_m1 [N_NODES * 2];  // p1 fp16x16 (32B/node)
__device__ __align__(16) uint4  g_m2 [N_NODES];      // p2 fp16x8  (16B/node)
__device__ __align__(16) uint2  g_m3 [N_NODES];      // p3 fp16x4  (8B/node)
__device__ __align__(16) float4 g_r1 [N_NODES * 4];  // r1 = x@W1r + b1 (fp32)
__device__ __align__(16) float4 g_r2 [N_NODES * 2];  // r2 (fp32)
__device__ __align__(16) float4 g_r3 [N_NODES];      // r3 (fp32)
__device__ __align__(16) int    g_deg[N_NODES];
__device__ __align__(16) int    g_off[N_NODES];
__device__ __align__(16) int    g_cur[N_NODES];
__device__ __align__(16) int    g_csr[N_EDGES];
__device__ __align__(16) int    g_bsum[SCAN_NBLK + 16];
__device__ __align__(16) float  g_pool[N_GRAPHS * 4];
__device__ __align__(16) float  g_gcnt[N_GRAPHS];

__device__ __forceinline__ float lrelu(float v) { return v > 0.f ? v : 0.01f * v; }
__device__ __forceinline__ unsigned pack_h2(float a, float b) {
    __half2 h = __floats2half2_rn(a, b);
    return *reinterpret_cast<unsigned*>(&h);
}
__device__ __forceinline__ float2 unpack_h2(unsigned u) {
    __half2 h = *reinterpret_cast<__half2*>(&u);
    return __half22float2(h);
}
__device__ __forceinline__ void acc_u4(float* a, uint4 u) {
    float2 f0 = unpack_h2(u.x), f1 = unpack_h2(u.y), f2 = unpack_h2(u.z), f3 = unpack_h2(u.w);
    a[0] += f0.x; a[1] += f0.y; a[2] += f1.x; a[3] += f1.y;
    a[4] += f2.x; a[5] += f2.y; a[6] += f3.x; a[7] += f3.y;
}

// ---------------- zero ----------------
__global__ void k_zero() {
    int i = blockIdx.x * blockDim.x + threadIdx.x;
    int stride = gridDim.x * blockDim.x;
    for (int j = i; j < N_NODES / 4; j += stride) ((int4*)g_deg)[j] = make_int4(0,0,0,0);
    for (int j = i; j < N_GRAPHS;    j += stride) ((float4*)g_pool)[j] = make_float4(0,0,0,0);
    for (int j = i; j < N_GRAPHS/4;  j += stride) ((float4*)g_gcnt)[j] = make_float4(0,0,0,0);
}

// ---------------- degree count ----------------
__global__ void k_count(const int* __restrict__ ei) {
    int e = blockIdx.x * blockDim.x + threadIdx.x;
    if (e >= N_EDGES) return;
    atomicAdd(&g_deg[ei[N_EDGES + e]], 1);
}

// ---------------- scan 1 ----------------
__global__ void k_scan1() {
    __shared__ int s[256];
    int t = threadIdx.x;
    int base = blockIdx.x * SCAN_CHUNK + t * 4;
    int d0 = (base + 0 < N_NODES) ? g_deg[base + 0] : 0;
    int d1 = (base + 1 < N_NODES) ? g_deg[base + 1] : 0;
    int d2 = (base + 2 < N_NODES) ? g_deg[base + 2] : 0;
    int d3 = (base + 3 < N_NODES) ? g_deg[base + 3] : 0;
    int tot = d0 + d1 + d2 + d3;
    s[t] = tot;
    __syncthreads();
    int v = tot;
    #pragma unroll
    for (int off = 1; off < 256; off <<= 1) {
        int u = (t >= off) ? s[t - off] : 0;
        __syncthreads();
        v += u; s[t] = v;
        __syncthreads();
    }
    int ex = v - tot;
    if (base + 0 < N_NODES) g_off[base + 0] = ex;
    if (base + 1 < N_NODES) g_off[base + 1] = ex + d0;
    if (base + 2 < N_NODES) g_off[base + 2] = ex + d0 + d1;
    if (base + 3 < N_NODES) g_off[base + 3] = ex + d0 + d1 + d2;
    if (t == 255) g_bsum[blockIdx.x] = v;
}

// ---------------- scan 2 ----------------
__global__ void k_scan2() {
    __shared__ int s[256];
    int t = threadIdx.x;
    int val = (t < SCAN_NBLK) ? g_bsum[t] : 0;
    s[t] = val;
    __syncthreads();
    int v = val;
    #pragma unroll
    for (int off = 1; off < 256; off <<= 1) {
        int u = (t >= off) ? s[t - off] : 0;
        __syncthreads();
        v += u; s[t] = v;
        __syncthreads();
    }
    if (t < SCAN_NBLK) g_bsum[t] = v - val;
}

// ---------------- scan 3 ----------------
__global__ void k_scan3() {
    int i = blockIdx.x * blockDim.x + threadIdx.x;
    if (i >= N_NODES) return;
    int off = g_off[i] + g_bsum[i / SCAN_CHUNK];
    g_off[i] = off;
    g_cur[i] = off;
}

// ---------------- CSR fill ----------------
__global__ void k_fill(const int* __restrict__ ei) {
    int e = blockIdx.x * blockDim.x + threadIdx.x;
    if (e >= N_EDGES) return;
    int s = ei[e];
    int d = ei[N_EDGES + e];
    int slot = atomicAdd(&g_cur[d], 1);
    g_csr[slot] = s;
}

// ---------------- proj1: m1 = fp16(x@W1l); r1 = x@W1r + b1 ----------------
__global__ void k_proj1(const float* __restrict__ x, const float* __restrict__ W1l,
                        const float* __restrict__ W1r, const float* __restrict__ b1) {
    __shared__ float sWl[13 * 16], sWr[13 * 16], sb[16];
    if (threadIdx.x < 13 * 16) { sWl[threadIdx.x] = W1l[threadIdx.x]; sWr[threadIdx.x] = W1r[threadIdx.x]; }
    if (threadIdx.x < 16) sb[threadIdx.x] = b1[threadIdx.x];
    __syncthreads();
    int i = blockIdx.x * blockDim.x + threadIdx.x;
    if (i >= N_NODES) return;
    float xv[13];
    const float* xr = x + (size_t)i * 13;
    #pragma unroll
    for (int k = 0; k < 13; k++) xv[k] = xr[k];
    float p[16], r[16];
    #pragma unroll
    for (int j = 0; j < 16; j++) {
        float a = 0.f, c = sb[j];
        #pragma unroll
        for (int k = 0; k < 13; k++) { a += xv[k] * sWl[k * 16 + j]; c += xv[k] * sWr[k * 16 + j]; }
        p[j] = a; r[j] = c;
    }
    g_m1[i * 2 + 0] = make_uint4(pack_h2(p[0],p[1]),  pack_h2(p[2],p[3]),
                                 pack_h2(p[4],p[5]),  pack_h2(p[6],p[7]));
    g_m1[i * 2 + 1] = make_uint4(pack_h2(p[8],p[9]),  pack_h2(p[10],p[11]),
                                 pack_h2(p[12],p[13]),pack_h2(p[14],p[15]));
    float4* rp = g_r1 + (size_t)i * 4;
    #pragma unroll
    for (int c = 0; c < 4; c++)
        rp[c] = make_float4(r[c*4+0], r[c*4+1], r[c*4+2], r[c*4+3]);
}

// ---------------- pull1: agg(m1)->h1 -> m2 (fp16), r2 (fp32) ----------------
__global__ void k_pull1(const float* __restrict__ W2l, const float* __restrict__ W2r,
                        const float* __restrict__ b2) {
    __shared__ float sWl[16 * 8], sWr[16 * 8], sb[8];
    if (threadIdx.x < 128) { sWl[threadIdx.x] = W2l[threadIdx.x]; sWr[threadIdx.x] = W2r[threadIdx.x]; }
    if (threadIdx.x < 8) sb[threadIdx.x] = b2[threadIdx.x];
    __syncthreads();
    int i = blockIdx.x * blockDim.x + threadIdx.x;
    if (i >= N_NODES) return;
    int deg = g_deg[i];
    int e = g_off[i], end = e + deg;
    float agg[16];
    #pragma unroll
    for (int k = 0; k < 16; k++) agg[k] = 0.f;
    if ((e & 1) && e < end) {
        const uint4* m = g_m1 + (size_t)g_csr[e] * 2;
        acc_u4(agg, m[0]); acc_u4(agg + 8, m[1]);
        e++;
    }
    for (; e + 2 <= end; e += 2) {
        int2 s2 = *(const int2*)(g_csr + e);
        const uint4* ma = g_m1 + (size_t)s2.x * 2;
        const uint4* mb = g_m1 + (size_t)s2.y * 2;
        uint4 u0 = ma[0], u1 = ma[1], v0 = mb[0], v1 = mb[1];
        acc_u4(agg, u0); acc_u4(agg + 8, u1);
        acc_u4(agg, v0); acc_u4(agg + 8, v1);
    }
    if (e < end) {
        const uint4* m = g_m1 + (size_t)g_csr[e] * 2;
        acc_u4(agg, m[0]); acc_u4(agg + 8, m[1]);
    }
    float inv = 1.0f / fmaxf((float)deg, 1.0f);
    const float4* r1p = g_r1 + (size_t)i * 4;
    float h[16];
    #pragma unroll
    for (int c = 0; c < 4; c++) {
        float4 rv = r1p[c];
        h[c*4+0] = lrelu(agg[c*4+0] * inv + rv.x);
        h[c*4+1] = lrelu(agg[c*4+1] * inv + rv.y);
        h[c*4+2] = lrelu(agg[c*4+2] * inv + rv.z);
        h[c*4+3] = lrelu(agg[c*4+3] * inv + rv.w);
    }
    float p[8], r[8];
    #pragma unroll
    for (int j = 0; j < 8; j++) {
        float a = 0.f, c = sb[j];
        #pragma unroll
        for (int k = 0; k < 16; k++) { a += h[k] * sWl[k * 8 + j]; c += h[k] * sWr[k * 8 + j]; }
        p[j] = a; r[j] = c;
    }
    g_m2[i] = make_uint4(pack_h2(p[0],p[1]), pack_h2(p[2],p[3]),
                         pack_h2(p[4],p[5]), pack_h2(p[6],p[7]));
    float4* rp = g_r2 + (size_t)i * 2;
    rp[0] = make_float4(r[0],r[1],r[2],r[3]);
    rp[1] = make_float4(r[4],r[5],r[6],r[7]);
}

// ---------------- pull2: agg(m2)->h2 -> m3 (fp16), r3 (fp32) ----------------
__global__ void k_pull2(const float* __restrict__ W3l, const float* __restrict__ W3r,
                        const float* __restrict__ b3) {
    __shared__ float sWl[8 * 4], sWr[8 * 4], sb[4];
    if (threadIdx.x < 32) { sWl[threadIdx.x] = W3l[threadIdx.x]; sWr[threadIdx.x] = W3r[threadIdx.x]; }
    if (threadIdx.x < 4) sb[threadIdx.x] = b3[threadIdx.x];
    __syncthreads();
    int i = blockIdx.x * blockDim.x + threadIdx.x;
    if (i >= N_NODES) return;
    int deg = g_deg[i];
    int e = g_off[i], end = e + deg;
    float agg[8];
    #pragma unroll
    for (int k = 0; k < 8; k++) agg[k] = 0.f;
    while ((e & 3) && e < end) { acc_u4(agg, g_m2[g_csr[e]]); e++; }
    for (; e + 4 <= end; e += 4) {
        int4 s4 = *(const int4*)(g_csr + e);
        uint4 u = g_m2[s4.x], v = g_m2[s4.y], w = g_m2[s4.z], y = g_m2[s4.w];
        acc_u4(agg, u); acc_u4(agg, v); acc_u4(agg, w); acc_u4(agg, y);
    }
    for (; e < end; e++) acc_u4(agg, g_m2[g_csr[e]]);
    float inv = 1.0f / fmaxf((float)deg, 1.0f);
    const float4* r2p = g_r2 + (size_t)i * 2;
    float4 rA = r2p[0], rB = r2p[1];
    float h[8];
    h[0] = lrelu(agg[0]*inv + rA.x); h[1] = lrelu(agg[1]*inv + rA.y);
    h[2] = lrelu(agg[2]*inv + rA.z); h[3] = lrelu(agg[3]*inv + rA.w);
    h[4] = lrelu(agg[4]*inv + rB.x); h[5] = lrelu(agg[5]*inv + rB.y);
    h[6] = lrelu(agg[6]*inv + rB.z); h[7] = lrelu(agg[7]*inv + rB.w);
    float p[4], r[4];
    #pragma unroll
    for (int j = 0; j < 4; j++) {
        float a = 0.f, c = sb[j];
        #pragma unroll
        for (int k = 0; k < 8; k++) { a += h[k] * sWl[k * 4 + j]; c += h[k] * sWr[k * 4 + j]; }
        p[j] = a; r[j] = c;
    }
    g_m3[i] = make_uint2(pack_h2(p[0],p[1]), pack_h2(p[2],p[3]));
    g_r3[i] = make_float4(r[0], r[1], r[2], r[3]);
}

// ---------------- pull3: agg(m3) + r3 -> o ; pooled ----------------
__global__ void k_pull3(const int* __restrict__ batch) {
    int i = blockIdx.x * blockDim.x + threadIdx.x;
    unsigned mask = __ballot_sync(0xffffffffu, i < N_NODES);
    if (i >= N_NODES) return;
    int deg = g_deg[i];
    int e = g_off[i], end = e + deg;
    float a0 = 0.f, a1 = 0.f, a2 = 0.f, a3 = 0.f;
    while ((e & 3) && e < end) {
        uint2 m = g_m3[g_csr[e]];
        float2 f0 = unpack_h2(m.x), f1 = unpack_h2(m.y);
        a0 += f0.x; a1 += f0.y; a2 += f1.x; a3 += f1.y;
        e++;
    }
    for (; e + 4 <= end; e += 4) {
        int4 s4 = *(const int4*)(g_csr + e);
        uint2 mu = g_m3[s4.x], mv = g_m3[s4.y], mw = g_m3[s4.z], my = g_m3[s4.w];
        float2 f;
        f = unpack_h2(mu.x); a0 += f.x; a1 += f.y; f = unpack_h2(mu.y); a2 += f.x; a3 += f.y;
        f = unpack_h2(mv.x); a0 += f.x; a1 += f.y; f = unpack_h2(mv.y); a2 += f.x; a3 += f.y;
        f = unpack_h2(mw.x); a0 += f.x; a1 += f.y; f = unpack_h2(mw.y); a2 += f.x; a3 += f.y;
        f = unpack_h2(my.x); a0 += f.x; a1 += f.y; f = unpack_h2(my.y); a2 += f.x; a3 += f.y;
    }
    for (; e < end; e++) {
        uint2 m = g_m3[g_csr[e]];
        float2 f0 = unpack_h2(m.x), f1 = unpack_h2(m.y);
        a0 += f0.x; a1 += f0.y; a2 += f1.x; a3 += f1.y;
    }
    float inv = 1.0f / fmaxf((float)deg, 1.0f);
    float4 rv = g_r3[i];
    float o[4] = { a0*inv + rv.x, a1*inv + rv.y, a2*inv + rv.z, a3*inv + rv.w };
    int g = batch[i];
    bool full = (mask == 0xffffffffu);
    int g0 = __shfl_sync(mask, g, 0);
    bool uni = full && __all_sync(0xffffffffu, g == g0);
    if (uni) {
        float c = 1.0f;
        #pragma unroll
        for (int off = 16; off; off >>= 1) {
            #pragma unroll
            for (int j = 0; j < 4; j++) o[j] += __shfl_xor_sync(0xffffffffu, o[j], off);
            c += __shfl_xor_sync(0xffffffffu, c, off);
        }
        if ((threadIdx.x & 31) == 0) {
            #pragma unroll
            for (int j = 0; j < 4; j++) atomicAdd(&g_pool[g * 4 + j], o[j]);
            atomicAdd(&g_gcnt[g], c);
        }
    } else {
        #pragma unroll
        for (int j = 0; j < 4; j++) atomicAdd(&g_pool[g * 4 + j], o[j]);
        atomicAdd(&g_gcnt[g], 1.0f);
    }
}

// ---------------- final ----------------
__global__ void k_final(const float* __restrict__ Wc, const float* __restrict__ bc,
                        float* __restrict__ out) {
    int g = blockIdx.x * blockDim.x + threadIdx.x;
    if (g >= N_GRAPHS) return;
    float gc = fmaxf(g_gcnt[g], 1.0f);
    float acc = bc[0];
    #pragma unroll
    for (int j = 0; j < 4; j++) {
        float ap = g_pool[g * 4 + j];
        acc += (ap / gc) * Wc[j] + ap * Wc[4 + j];
    }
    out[g] = acc;
}

extern "C" void kernel_launch(void* const* d_in, const int* in_sizes, int n_in,
                              void* d_out, int out_size) {
    const float* x     = (const float*)d_in[0];
    const int*   eidx  = (const int*)d_in[1];   // int32 on device (JAX x64 off)
    const int*   batch = (const int*)d_in[2];
    const float* W1l = (const float*)d_in[3];
    const float* b1  = (const float*)d_in[4];
    const float* W1r = (const float*)d_in[5];
    const float* W2l = (const float*)d_in[6];
    const float* b2  = (const float*)d_in[7];
    const float* W2r = (const float*)d_in[8];
    const float* W3l = (const float*)d_in[9];
    const float* b3  = (const float*)d_in[10];
    const float* W3r = (const float*)d_in[11];
    const float* Wc  = (const float*)d_in[12];
    const float* bc  = (const float*)d_in[13];
    float* out = (float*)d_out;

    const int TB = 256;
    const int nblk = (N_NODES + TB - 1) / TB;
    const int eblk = (N_EDGES + TB - 1) / TB;

    k_zero <<<256, TB>>>();
    k_count<<<eblk, TB>>>(eidx);
    k_scan1<<<SCAN_NBLK, 256>>>();
    k_scan2<<<1, 256>>>();
    k_scan3<<<nblk, TB>>>();
    k_fill <<<eblk, TB>>>(eidx);
    k_proj1<<<nblk, TB>>>(x, W1l, W1r, b1);
    k_pull1<<<nblk, TB>>>(W2l, W2r, b2);
    k_pull2<<<nblk, TB>>>(W3l, W3r, b3);
    k_pull3<<<nblk, TB>>>(batch);
    k_final<<<2, TB>>>(Wc, bc, out);
}